// round 16
// baseline (speedup 1.0000x reference)
#include <cuda_runtime.h>
#include <cuda_bf16.h>
#include <cstdint>

// Problem constants
#define S      2048
#define E      2048
#define HQ     32
#define HKV    8
#define D      64
#define QSTRIDE (HQ*D)    // 2048
#define KSTRIDE (HKV*D)   // 512
#define NTOT   (QSTRIDE + 2*KSTRIDE)  // 3072

// ---------------- scratch (device globals; no allocation allowed) ----------
__device__ float g_Q[S * QSTRIDE];
__device__ float g_K[S * KSTRIDE];
__device__ float g_V[S * KSTRIDE];
__device__ float g_A[S * QSTRIDE];

// ---------------- helpers ---------------------------------------------------
__device__ __forceinline__ unsigned f2t(float f) {
    unsigned u;
    asm("cvt.rna.tf32.f32 %0, %1;" : "=r"(u) : "f"(f));
    return u;
}

__device__ __forceinline__ void mma_tf32(float c[4],
                                         unsigned a0, unsigned a1, unsigned a2, unsigned a3,
                                         unsigned b0, unsigned b1) {
    asm volatile(
        "mma.sync.aligned.m16n8k8.row.col.f32.tf32.tf32.f32 "
        "{%0,%1,%2,%3}, {%4,%5,%6,%7}, {%8,%9}, {%0,%1,%2,%3};\n"
        : "+f"(c[0]), "+f"(c[1]), "+f"(c[2]), "+f"(c[3])
        : "r"(a0), "r"(a1), "r"(a2), "r"(a3), "r"(b0), "r"(b1));
}

// GEMM smem geometry: A row-major [128][36], B [32][136], double buffered.
#define AP   36
#define BP   136
#define ASZ  (128 * AP)
#define BSZ  (32 * BP)
#define GEMM_SMEM_BYTES ((2 * ASZ + 2 * BSZ) * 4)   // 71680

// ============================================================================
// GEMM core (exact R5 design — crossbar-bound local optimum, frozen).
// ============================================================================
struct GemmCore {
    template <bool ROPE_EPI>
    static __device__ __forceinline__ void run(
        const float* __restrict__ A, const float* __restrict__ B,
        float* __restrict__ C, const float* __restrict__ F,
        int N, int K, int mbase, int nbase_local) {

        extern __shared__ unsigned smg[];
        unsigned* AsBuf = smg;
        unsigned* BsBuf = smg + 2 * ASZ;

        const int tid  = threadIdx.x;
        const int lane = tid & 31;
        const int warp = tid >> 5;
        const int m0w = (warp >> 1) * 64;
        const int n0w = (warp & 1) * 64;
        const int qr = lane >> 2, qc = lane & 3;

        float acc[4][8][4];
#pragma unroll
        for (int mt = 0; mt < 4; ++mt)
#pragma unroll
            for (int nt = 0; nt < 8; ++nt)
#pragma unroll
                for (int j = 0; j < 4; ++j) acc[mt][nt][j] = 0.f;

        const int arow = tid >> 3, af4 = tid & 7;
        const int brow = tid >> 5, bf4 = tid & 31;

        float4 pa[8], pb[8];

#pragma unroll
        for (int i = 0; i < 8; ++i)
            pa[i] = *(const float4*)&A[(size_t)(mbase + arow + i * 16) * K + af4 * 4];
#pragma unroll
        for (int i = 0; i < 8; ++i)
            pb[i] = *(const float4*)&B[(size_t)(brow + i * 4) * N + nbase_local + bf4 * 4];
#pragma unroll
        for (int i = 0; i < 8; ++i) {
            int r = arow + i * 16;
            uint4 u = make_uint4(f2t(pa[i].x), f2t(pa[i].y), f2t(pa[i].z), f2t(pa[i].w));
            *(uint4*)&AsBuf[r * AP + af4 * 4] = u;
        }
#pragma unroll
        for (int i = 0; i < 8; ++i) {
            int r = brow + i * 4;
            uint4 u = make_uint4(f2t(pb[i].x), f2t(pb[i].y), f2t(pb[i].z), f2t(pb[i].w));
            *(uint4*)&BsBuf[r * BP + bf4 * 4] = u;
        }
        if (32 < K) {
#pragma unroll
            for (int i = 0; i < 8; ++i)
                pa[i] = *(const float4*)&A[(size_t)(mbase + arow + i * 16) * K + 32 + af4 * 4];
#pragma unroll
            for (int i = 0; i < 8; ++i)
                pb[i] = *(const float4*)&B[(size_t)(32 + brow + i * 4) * N + nbase_local + bf4 * 4];
        }
        __syncthreads();

        int buf = 0;
        for (int kb = 0; kb < K; kb += 32) {
            unsigned* Asb = AsBuf + buf * ASZ;
            unsigned* Bsb = BsBuf + buf * BSZ;

            if (kb + 32 < K) {
                unsigned* Asn = AsBuf + (buf ^ 1) * ASZ;
                unsigned* Bsn = BsBuf + (buf ^ 1) * BSZ;
#pragma unroll
                for (int i = 0; i < 8; ++i) {
                    int r = arow + i * 16;
                    uint4 u = make_uint4(f2t(pa[i].x), f2t(pa[i].y), f2t(pa[i].z), f2t(pa[i].w));
                    *(uint4*)&Asn[r * AP + af4 * 4] = u;
                }
#pragma unroll
                for (int i = 0; i < 8; ++i) {
                    int r = brow + i * 4;
                    uint4 u = make_uint4(f2t(pb[i].x), f2t(pb[i].y), f2t(pb[i].z), f2t(pb[i].w));
                    *(uint4*)&Bsn[r * BP + bf4 * 4] = u;
                }
            }
            if (kb + 64 < K) {
#pragma unroll
                for (int i = 0; i < 8; ++i)
                    pa[i] = *(const float4*)&A[(size_t)(mbase + arow + i * 16) * K + kb + 64 + af4 * 4];
#pragma unroll
                for (int i = 0; i < 8; ++i)
                    pb[i] = *(const float4*)&B[(size_t)(kb + 64 + brow + i * 4) * N + nbase_local + bf4 * 4];
            }

#pragma unroll
            for (int ks = 0; ks < 4; ++ks) {
                const int k0 = ks * 8;
                unsigned a[4][4];
#pragma unroll
                for (int mt = 0; mt < 4; ++mt) {
                    int m = m0w + mt * 16;
                    a[mt][0] = Asb[(m + qr) * AP + k0 + qc];
                    a[mt][1] = Asb[(m + 8 + qr) * AP + k0 + qc];
                    a[mt][2] = Asb[(m + qr) * AP + k0 + 4 + qc];
                    a[mt][3] = Asb[(m + 8 + qr) * AP + k0 + 4 + qc];
                }
#pragma unroll
                for (int nt = 0; nt < 8; ++nt) {
                    int n = n0w + nt * 8;
                    unsigned b0 = Bsb[(k0 + qc) * BP + n + qr];
                    unsigned b1 = Bsb[(k0 + 4 + qc) * BP + n + qr];
#pragma unroll
                    for (int mt = 0; mt < 4; ++mt)
                        mma_tf32(acc[mt][nt], a[mt][0], a[mt][1], a[mt][2], a[mt][3], b0, b1);
                }
            }
            __syncthreads();
            buf ^= 1;
        }

#pragma unroll
        for (int mt = 0; mt < 4; ++mt) {
#pragma unroll
            for (int nt = 0; nt < 8; ++nt) {
                int row = mbase + m0w + mt * 16 + qr;
                int lcol = nbase_local + n0w + nt * 8 + 2 * qc;
                float2 v0 = make_float2(acc[mt][nt][0], acc[mt][nt][1]);
                float2 v1 = make_float2(acc[mt][nt][2], acc[mt][nt][3]);
                if (ROPE_EPI) {
                    int d = lcol & 63;
                    float2 f0 = *(const float2*)&F[(size_t)row * 64 + d];
                    float2 f1 = *(const float2*)&F[(size_t)(row + 8) * 64 + d];
                    v0 = make_float2(v0.x * f0.x - v0.y * f0.y, v0.x * f0.y + v0.y * f0.x);
                    v1 = make_float2(v1.x * f1.x - v1.y * f1.y, v1.x * f1.y + v1.y * f1.x);
                }
                *(float2*)&C[(size_t)row * N + lcol] = v0;
                *(float2*)&C[(size_t)(row + 8) * N + lcol] = v1;
            }
        }
    }
};

__global__ __launch_bounds__(128)
void qkv_gemm_kernel(const float* __restrict__ A,
                     const float* __restrict__ Wq,
                     const float* __restrict__ Wk,
                     const float* __restrict__ Wv,
                     const float* __restrict__ F,
                     float* __restrict__ Qp,
                     float* __restrict__ Kp,
                     float* __restrict__ Vp) {
    const int mbase = blockIdx.y * 128;
    const int nbase = blockIdx.x * 128;
    if (nbase < QSTRIDE) {
        GemmCore::run<true>(A, Wq, Qp, F, QSTRIDE, E, mbase, nbase);
    } else if (nbase < QSTRIDE + KSTRIDE) {
        GemmCore::run<true>(A, Wk, Kp, F, KSTRIDE, E, mbase, nbase - QSTRIDE);
    } else {
        GemmCore::run<false>(A, Wv, Vp, nullptr, KSTRIDE, E, mbase,
                             nbase - QSTRIDE - KSTRIDE);
    }
}

__global__ __launch_bounds__(128)
void tgemm_kernel(const float* __restrict__ A,
                  const float* __restrict__ B,
                  float* __restrict__ C,
                  int M, int N, int K) {
    GemmCore::run<false>(A, B, C, nullptr, N, K, blockIdx.y * 128, blockIdx.x * 128);
}

// ============================================================================
// TF32 flash attention (R14 base + K/V tile 128 with two 64-col sub-passes).
// 128 q-rows/CTA, 4 warps x 32 rows (mt=2, nt=8); Q fragments hoisted to
// registers; Ps overlaid on Qs; one outer load + 2 barriers per 128 k-cols.
// smem 104 KB -> 2 CTAs/SM; __launch_bounds__(128, 2).
// ============================================================================
#define FPQ 68
#define FPV 72
#define FA_SMEM_WORDS (128*FPQ + 128*FPQ + 128*FPV)   // QsPs + Ks(128) + Vs(128)
#define FA_SMEM_BYTES (FA_SMEM_WORDS * 4)              // 106496

__global__ __launch_bounds__(128, 2)
void flash_tc_kernel(const float* __restrict__ Q,
                     const float* __restrict__ Kg,
                     const float* __restrict__ Vg,
                     float* __restrict__ O) {
    const int h = blockIdx.y;
    const int qt = (gridDim.x - 1) - blockIdx.x;
    const int qbase = qt * 128;
    const int kh = h >> 2;

    extern __shared__ unsigned smu[];
    unsigned* QsPs = smu;                  // [128][FPQ]  Q tile, then P
    unsigned* Ks   = QsPs + 128 * FPQ;     // [128][FPQ]
    unsigned* Vs   = Ks + 128 * FPQ;       // [128][FPV] row-major [k][d]

    const int tid = threadIdx.x;
    const int lane = tid & 31;
    const int warp = tid >> 5;
    const int m0 = warp * 32;
    const int qr = lane >> 2;
    const int qc = lane & 3;
    const int f4 = tid & 15;
    const int row0 = tid >> 4;

    // ---- load Q tile (128 x 64) ----
#pragma unroll
    for (int i = 0; i < 16; ++i) {
        int r = row0 + i * 8;
        float4 v = *(const float4*)&Q[(size_t)(qbase + r) * QSTRIDE + h * D + f4 * 4];
        uint4 u = make_uint4(f2t(v.x), f2t(v.y), f2t(v.z), f2t(v.w));
        *(uint4*)&QsPs[r * FPQ + f4 * 4] = u;
    }
    __syncthreads();

    // ---- hoist Q fragments (loop-invariant) into registers ----
    unsigned qa[8][2][4];
#pragma unroll
    for (int ks = 0; ks < 8; ++ks) {
        const int k0 = ks * 8;
#pragma unroll
        for (int mt = 0; mt < 2; ++mt) {
            int m = m0 + mt * 16;
            qa[ks][mt][0] = QsPs[(m + qr) * FPQ + k0 + qc];
            qa[ks][mt][1] = QsPs[(m + 8 + qr) * FPQ + k0 + qc];
            qa[ks][mt][2] = QsPs[(m + qr) * FPQ + k0 + 4 + qc];
            qa[ks][mt][3] = QsPs[(m + 8 + qr) * FPQ + k0 + 4 + qc];
        }
    }
    // From here on, QsPs serves as the P buffer (warp-private rows).

    float o[2][8][4];
#pragma unroll
    for (int mt = 0; mt < 2; ++mt)
#pragma unroll
        for (int nt = 0; nt < 8; ++nt)
#pragma unroll
            for (int j = 0; j < 4; ++j) o[mt][nt][j] = 0.f;
    float mr[2][2], lr[2][2];
#pragma unroll
    for (int mt = 0; mt < 2; ++mt) {
        mr[mt][0] = -1e30f; mr[mt][1] = -1e30f;
        lr[mt][0] = 0.f;    lr[mt][1] = 0.f;
    }

    for (int kt = 0; kt <= qt; ++kt) {
        __syncthreads();   // prior tile's K/V (and P) reads complete;
                           // also orders Q-frag extraction before P writes
        const int tbase = kt * 128;

        // load K tile (128 x 64)
#pragma unroll
        for (int i = 0; i < 16; ++i) {
            int r = row0 + i * 8;
            float4 v = *(const float4*)&Kg[(size_t)(tbase + r) * KSTRIDE + kh * D + f4 * 4];
            uint4 u = make_uint4(f2t(v.x), f2t(v.y), f2t(v.z), f2t(v.w));
            *(uint4*)&Ks[r * FPQ + f4 * 4] = u;
        }
        // load V tile (128 x 64) row-major [k][d]
#pragma unroll
        for (int i = 0; i < 16; ++i) {
            int r = row0 + i * 8;
            float4 v = *(const float4*)&Vg[(size_t)(tbase + r) * KSTRIDE + kh * D + f4 * 4];
            uint4 u = make_uint4(f2t(v.x), f2t(v.y), f2t(v.z), f2t(v.w));
            *(uint4*)&Vs[r * FPV + f4 * 4] = u;
        }
        __syncthreads();

        // ---- two 64-col sub-passes over this 128-row K/V tile ----
#pragma unroll
        for (int h2 = 0; h2 < 2; ++h2) {
            const int kbase = tbase + h2 * 64;
            if (kbase > qbase + m0 + 31) continue;   // warp-level causal skip
            unsigned* Ksb = Ks + h2 * 64 * FPQ;
            unsigned* Vsb = Vs + h2 * 64 * FPV;

            // ---- S = Q K^T (Q fragments from registers) ----
            float s[2][8][4];
#pragma unroll
            for (int mt = 0; mt < 2; ++mt)
#pragma unroll
                for (int nt = 0; nt < 8; ++nt)
#pragma unroll
                    for (int j = 0; j < 4; ++j) s[mt][nt][j] = 0.f;

#pragma unroll
            for (int ks = 0; ks < 8; ++ks) {
                const int k0 = ks * 8;
#pragma unroll
                for (int nt = 0; nt < 8; ++nt) {
                    unsigned b0 = Ksb[(nt * 8 + qr) * FPQ + k0 + qc];
                    unsigned b1 = Ksb[(nt * 8 + qr) * FPQ + k0 + 4 + qc];
#pragma unroll
                    for (int mt = 0; mt < 2; ++mt)
                        mma_tf32(s[mt][nt], qa[ks][mt][0], qa[ks][mt][1],
                                 qa[ks][mt][2], qa[ks][mt][3], b0, b1);
                }
            }

            // ---- scale + causal mask + online softmax (per mt) ----
#pragma unroll
            for (int mt = 0; mt < 2; ++mt) {
                const int q_lo = qbase + m0 + mt * 16 + qr;
                const int q_hi = q_lo + 8;
                const bool need_mask = (kbase + 63 > q_lo);
#pragma unroll
                for (int nt = 0; nt < 8; ++nt) {
#pragma unroll
                    for (int j = 0; j < 2; ++j) {
                        int kcol = kbase + nt * 8 + 2 * qc + j;
                        float v0 = s[mt][nt][j] * 0.125f;
                        float v1 = s[mt][nt][2 + j] * 0.125f;
                        if (need_mask && kcol > q_lo) v0 = -1e30f;
                        if (need_mask && kcol > q_hi) v1 = -1e30f;
                        s[mt][nt][j] = v0;
                        s[mt][nt][2 + j] = v1;
                    }
                }

                float tm_lo = -1e30f, tm_hi = -1e30f;
#pragma unroll
                for (int nt = 0; nt < 8; ++nt) {
                    tm_lo = fmaxf(tm_lo, fmaxf(s[mt][nt][0], s[mt][nt][1]));
                    tm_hi = fmaxf(tm_hi, fmaxf(s[mt][nt][2], s[mt][nt][3]));
                }
#pragma unroll
                for (int off = 1; off <= 2; off <<= 1) {
                    tm_lo = fmaxf(tm_lo, __shfl_xor_sync(0xffffffffu, tm_lo, off));
                    tm_hi = fmaxf(tm_hi, __shfl_xor_sync(0xffffffffu, tm_hi, off));
                }
                float mn_lo = fmaxf(mr[mt][0], tm_lo);
                float mn_hi = fmaxf(mr[mt][1], tm_hi);
                float fac_lo = __expf(mr[mt][0] - mn_lo);
                float fac_hi = __expf(mr[mt][1] - mn_hi);

                float sum_lo = 0.f, sum_hi = 0.f;
#pragma unroll
                for (int nt = 0; nt < 8; ++nt) {
                    float p0 = __expf(s[mt][nt][0] - mn_lo);
                    float p1 = __expf(s[mt][nt][1] - mn_lo);
                    float p2 = __expf(s[mt][nt][2] - mn_hi);
                    float p3 = __expf(s[mt][nt][3] - mn_hi);
                    s[mt][nt][0] = p0; s[mt][nt][1] = p1;
                    s[mt][nt][2] = p2; s[mt][nt][3] = p3;
                    sum_lo += p0 + p1;
                    sum_hi += p2 + p3;
                }
#pragma unroll
                for (int off = 1; off <= 2; off <<= 1) {
                    sum_lo += __shfl_xor_sync(0xffffffffu, sum_lo, off);
                    sum_hi += __shfl_xor_sync(0xffffffffu, sum_hi, off);
                }
                lr[mt][0] = lr[mt][0] * fac_lo + sum_lo;
                lr[mt][1] = lr[mt][1] * fac_hi + sum_hi;
                mr[mt][0] = mn_lo;
                mr[mt][1] = mn_hi;

#pragma unroll
                for (int nt = 0; nt < 8; ++nt) {
                    o[mt][nt][0] *= fac_lo; o[mt][nt][1] *= fac_lo;
                    o[mt][nt][2] *= fac_hi; o[mt][nt][3] *= fac_hi;
                }

                // write P fragments to smem (warp-private rows, overlaid on Qs)
#pragma unroll
                for (int nt = 0; nt < 8; ++nt) {
                    int r = m0 + mt * 16 + qr;
                    int c = nt * 8 + 2 * qc;
                    QsPs[r * FPQ + c]           = f2t(s[mt][nt][0]);
                    QsPs[r * FPQ + c + 1]       = f2t(s[mt][nt][1]);
                    QsPs[(r + 8) * FPQ + c]     = f2t(s[mt][nt][2]);
                    QsPs[(r + 8) * FPQ + c + 1] = f2t(s[mt][nt][3]);
                }
            }
            __syncwarp();

            // ---- O += P V ----
#pragma unroll
            for (int ks = 0; ks < 8; ++ks) {
                const int k0 = ks * 8;
                unsigned a[2][4];
#pragma unroll
                for (int mt = 0; mt < 2; ++mt) {
                    int m = m0 + mt * 16;
                    a[mt][0] = QsPs[(m + qr) * FPQ + k0 + qc];
                    a[mt][1] = QsPs[(m + 8 + qr) * FPQ + k0 + qc];
                    a[mt][2] = QsPs[(m + qr) * FPQ + k0 + 4 + qc];
                    a[mt][3] = QsPs[(m + 8 + qr) * FPQ + k0 + 4 + qc];
                }
#pragma unroll
                for (int nt = 0; nt < 8; ++nt) {
                    unsigned b0 = Vsb[(k0 + qc) * FPV + nt * 8 + qr];
                    unsigned b1 = Vsb[(k0 + 4 + qc) * FPV + nt * 8 + qr];
#pragma unroll
                    for (int mt = 0; mt < 2; ++mt)
                        mma_tf32(o[mt][nt], a[mt][0], a[mt][1], a[mt][2], a[mt][3], b0, b1);
                }
            }
            __syncwarp();   // P reads done before next sub-pass rewrites P
        }
    }

    // ---- normalize + write out ----
#pragma unroll
    for (int mt = 0; mt < 2; ++mt) {
        float inv_lo = 1.f / lr[mt][0];
        float inv_hi = 1.f / lr[mt][1];
#pragma unroll
        for (int nt = 0; nt < 8; ++nt) {
            int row = qbase + m0 + mt * 16 + qr;
            int col = h * D + nt * 8 + 2 * qc;
            *(float2*)&O[(size_t)row * QSTRIDE + col] =
                make_float2(o[mt][nt][0] * inv_lo, o[mt][nt][1] * inv_lo);
            *(float2*)&O[(size_t)(row + 8) * QSTRIDE + col] =
                make_float2(o[mt][nt][2] * inv_hi, o[mt][nt][3] * inv_hi);
        }
    }
}

// ---------------- launch ---------------------------------------------------
extern "C" void kernel_launch(void* const* d_in, const int* in_sizes, int n_in,
                              void* d_out, int out_size) {
    const float* x  = (const float*)d_in[0];
    const float* fc = (const float*)d_in[1];
    const float* Wq = (const float*)d_in[3];
    const float* Wk = (const float*)d_in[4];
    const float* Wv = (const float*)d_in[5];
    const float* Wo = (const float*)d_in[6];
    float* out = (float*)d_out;

    float *Q, *K, *V, *A;
    cudaGetSymbolAddress((void**)&Q, g_Q);
    cudaGetSymbolAddress((void**)&K, g_K);
    cudaGetSymbolAddress((void**)&V, g_V);
    cudaGetSymbolAddress((void**)&A, g_A);

    cudaFuncSetAttribute(qkv_gemm_kernel,
                         cudaFuncAttributeMaxDynamicSharedMemorySize, GEMM_SMEM_BYTES);
    cudaFuncSetAttribute(tgemm_kernel,
                         cudaFuncAttributeMaxDynamicSharedMemorySize, GEMM_SMEM_BYTES);
    cudaFuncSetAttribute(flash_tc_kernel,
                         cudaFuncAttributeMaxDynamicSharedMemorySize, FA_SMEM_BYTES);

    // fused QKV projection + RoPE (Q,K only)
    qkv_gemm_kernel<<<dim3(NTOT / 128, S / 128), 128, GEMM_SMEM_BYTES>>>(
        x, Wq, Wk, Wv, fc, Q, K, V);

    // causal GQA flash attention (kv-tile 128, two sub-passes)
    flash_tc_kernel<<<dim3(S / 128, HQ), 128, FA_SMEM_BYTES>>>(Q, K, V, A);

    // output projection
    tgemm_kernel<<<dim3(E / 128, S / 128), 128, GEMM_SMEM_BYTES>>>(A, Wo, out, S, E, E);
}

// round 17
// speedup vs baseline: 1.1561x; 1.1561x over previous
#include <cuda_runtime.h>
#include <cuda_bf16.h>
#include <cstdint>

// Problem constants
#define S      2048
#define E      2048
#define HQ     32
#define HKV    8
#define D      64
#define QSTRIDE (HQ*D)    // 2048
#define KSTRIDE (HKV*D)   // 512
#define NTOT   (QSTRIDE + 2*KSTRIDE)  // 3072

// ---------------- scratch (device globals; no allocation allowed) ----------
__device__ float g_Q[S * QSTRIDE];
__device__ float g_K[S * KSTRIDE];
__device__ float g_V[S * KSTRIDE];
__device__ float g_A[S * QSTRIDE];

// ---------------- helpers ---------------------------------------------------
__device__ __forceinline__ unsigned f2t(float f) {
    unsigned u;
    asm("cvt.rna.tf32.f32 %0, %1;" : "=r"(u) : "f"(f));
    return u;
}

__device__ __forceinline__ void mma_tf32(float c[4],
                                         unsigned a0, unsigned a1, unsigned a2, unsigned a3,
                                         unsigned b0, unsigned b1) {
    asm volatile(
        "mma.sync.aligned.m16n8k8.row.col.f32.tf32.tf32.f32 "
        "{%0,%1,%2,%3}, {%4,%5,%6,%7}, {%8,%9}, {%0,%1,%2,%3};\n"
        : "+f"(c[0]), "+f"(c[1]), "+f"(c[2]), "+f"(c[3])
        : "r"(a0), "r"(a1), "r"(a2), "r"(a3), "r"(b0), "r"(b1));
}

// GEMM smem geometry: A row-major [128][36], B [32][136], double buffered.
#define AP   36
#define BP   136
#define ASZ  (128 * AP)
#define BSZ  (32 * BP)
#define GEMM_SMEM_BYTES ((2 * ASZ + 2 * BSZ) * 4)   // 71680

// ============================================================================
// GEMM core (exact R5 design — crossbar-bound local optimum, frozen).
// ============================================================================
struct GemmCore {
    template <bool ROPE_EPI>
    static __device__ __forceinline__ void run(
        const float* __restrict__ A, const float* __restrict__ B,
        float* __restrict__ C, const float* __restrict__ F,
        int N, int K, int mbase, int nbase_local) {

        extern __shared__ unsigned smg[];
        unsigned* AsBuf = smg;
        unsigned* BsBuf = smg + 2 * ASZ;

        const int tid  = threadIdx.x;
        const int lane = tid & 31;
        const int warp = tid >> 5;
        const int m0w = (warp >> 1) * 64;
        const int n0w = (warp & 1) * 64;
        const int qr = lane >> 2, qc = lane & 3;

        float acc[4][8][4];
#pragma unroll
        for (int mt = 0; mt < 4; ++mt)
#pragma unroll
            for (int nt = 0; nt < 8; ++nt)
#pragma unroll
                for (int j = 0; j < 4; ++j) acc[mt][nt][j] = 0.f;

        const int arow = tid >> 3, af4 = tid & 7;
        const int brow = tid >> 5, bf4 = tid & 31;

        float4 pa[8], pb[8];

#pragma unroll
        for (int i = 0; i < 8; ++i)
            pa[i] = *(const float4*)&A[(size_t)(mbase + arow + i * 16) * K + af4 * 4];
#pragma unroll
        for (int i = 0; i < 8; ++i)
            pb[i] = *(const float4*)&B[(size_t)(brow + i * 4) * N + nbase_local + bf4 * 4];
#pragma unroll
        for (int i = 0; i < 8; ++i) {
            int r = arow + i * 16;
            uint4 u = make_uint4(f2t(pa[i].x), f2t(pa[i].y), f2t(pa[i].z), f2t(pa[i].w));
            *(uint4*)&AsBuf[r * AP + af4 * 4] = u;
        }
#pragma unroll
        for (int i = 0; i < 8; ++i) {
            int r = brow + i * 4;
            uint4 u = make_uint4(f2t(pb[i].x), f2t(pb[i].y), f2t(pb[i].z), f2t(pb[i].w));
            *(uint4*)&BsBuf[r * BP + bf4 * 4] = u;
        }
        if (32 < K) {
#pragma unroll
            for (int i = 0; i < 8; ++i)
                pa[i] = *(const float4*)&A[(size_t)(mbase + arow + i * 16) * K + 32 + af4 * 4];
#pragma unroll
            for (int i = 0; i < 8; ++i)
                pb[i] = *(const float4*)&B[(size_t)(32 + brow + i * 4) * N + nbase_local + bf4 * 4];
        }
        __syncthreads();

        int buf = 0;
        for (int kb = 0; kb < K; kb += 32) {
            unsigned* Asb = AsBuf + buf * ASZ;
            unsigned* Bsb = BsBuf + buf * BSZ;

            if (kb + 32 < K) {
                unsigned* Asn = AsBuf + (buf ^ 1) * ASZ;
                unsigned* Bsn = BsBuf + (buf ^ 1) * BSZ;
#pragma unroll
                for (int i = 0; i < 8; ++i) {
                    int r = arow + i * 16;
                    uint4 u = make_uint4(f2t(pa[i].x), f2t(pa[i].y), f2t(pa[i].z), f2t(pa[i].w));
                    *(uint4*)&Asn[r * AP + af4 * 4] = u;
                }
#pragma unroll
                for (int i = 0; i < 8; ++i) {
                    int r = brow + i * 4;
                    uint4 u = make_uint4(f2t(pb[i].x), f2t(pb[i].y), f2t(pb[i].z), f2t(pb[i].w));
                    *(uint4*)&Bsn[r * BP + bf4 * 4] = u;
                }
            }
            if (kb + 64 < K) {
#pragma unroll
                for (int i = 0; i < 8; ++i)
                    pa[i] = *(const float4*)&A[(size_t)(mbase + arow + i * 16) * K + kb + 64 + af4 * 4];
#pragma unroll
                for (int i = 0; i < 8; ++i)
                    pb[i] = *(const float4*)&B[(size_t)(kb + 64 + brow + i * 4) * N + nbase_local + bf4 * 4];
            }

#pragma unroll
            for (int ks = 0; ks < 4; ++ks) {
                const int k0 = ks * 8;
                unsigned a[4][4];
#pragma unroll
                for (int mt = 0; mt < 4; ++mt) {
                    int m = m0w + mt * 16;
                    a[mt][0] = Asb[(m + qr) * AP + k0 + qc];
                    a[mt][1] = Asb[(m + 8 + qr) * AP + k0 + qc];
                    a[mt][2] = Asb[(m + qr) * AP + k0 + 4 + qc];
                    a[mt][3] = Asb[(m + 8 + qr) * AP + k0 + 4 + qc];
                }
#pragma unroll
                for (int nt = 0; nt < 8; ++nt) {
                    int n = n0w + nt * 8;
                    unsigned b0 = Bsb[(k0 + qc) * BP + n + qr];
                    unsigned b1 = Bsb[(k0 + 4 + qc) * BP + n + qr];
#pragma unroll
                    for (int mt = 0; mt < 4; ++mt)
                        mma_tf32(acc[mt][nt], a[mt][0], a[mt][1], a[mt][2], a[mt][3], b0, b1);
                }
            }
            __syncthreads();
            buf ^= 1;
        }

#pragma unroll
        for (int mt = 0; mt < 4; ++mt) {
#pragma unroll
            for (int nt = 0; nt < 8; ++nt) {
                int row = mbase + m0w + mt * 16 + qr;
                int lcol = nbase_local + n0w + nt * 8 + 2 * qc;
                float2 v0 = make_float2(acc[mt][nt][0], acc[mt][nt][1]);
                float2 v1 = make_float2(acc[mt][nt][2], acc[mt][nt][3]);
                if (ROPE_EPI) {
                    int d = lcol & 63;
                    float2 f0 = *(const float2*)&F[(size_t)row * 64 + d];
                    float2 f1 = *(const float2*)&F[(size_t)(row + 8) * 64 + d];
                    v0 = make_float2(v0.x * f0.x - v0.y * f0.y, v0.x * f0.y + v0.y * f0.x);
                    v1 = make_float2(v1.x * f1.x - v1.y * f1.y, v1.x * f1.y + v1.y * f1.x);
                }
                *(float2*)&C[(size_t)row * N + lcol] = v0;
                *(float2*)&C[(size_t)(row + 8) * N + lcol] = v1;
            }
        }
    }
};

__global__ __launch_bounds__(128)
void qkv_gemm_kernel(const float* __restrict__ A,
                     const float* __restrict__ Wq,
                     const float* __restrict__ Wk,
                     const float* __restrict__ Wv,
                     const float* __restrict__ F,
                     float* __restrict__ Qp,
                     float* __restrict__ Kp,
                     float* __restrict__ Vp) {
    const int mbase = blockIdx.y * 128;
    const int nbase = blockIdx.x * 128;
    if (nbase < QSTRIDE) {
        GemmCore::run<true>(A, Wq, Qp, F, QSTRIDE, E, mbase, nbase);
    } else if (nbase < QSTRIDE + KSTRIDE) {
        GemmCore::run<true>(A, Wk, Kp, F, KSTRIDE, E, mbase, nbase - QSTRIDE);
    } else {
        GemmCore::run<false>(A, Wv, Vp, nullptr, KSTRIDE, E, mbase,
                             nbase - QSTRIDE - KSTRIDE);
    }
}

__global__ __launch_bounds__(128)
void tgemm_kernel(const float* __restrict__ A,
                  const float* __restrict__ B,
                  float* __restrict__ C,
                  int M, int N, int K) {
    GemmCore::run<false>(A, B, C, nullptr, N, K, blockIdx.y * 128, blockIdx.x * 128);
}

// ============================================================================
// TF32 flash attention (R14 inner body, unchanged) processed as PAIRED
// q-tiles for causal load balance: CTA bx handles q-tiles (NT-1-bx) then bx
// — total work is constant (NT+1 kt-iterations). grid (NT/2, HQ) = one wave.
// ============================================================================
#define FPQ 68
#define FPV 72
#define FA_SMEM_WORDS (128*FPQ + 64*FPQ + 64*FPV)   // QsPs + Ks + Vs
#define FA_SMEM_BYTES (FA_SMEM_WORDS * 4)            // 70656

__device__ __forceinline__ void flash_one_tile(
    int qt, int h, int kh,
    const float* __restrict__ Q,
    const float* __restrict__ Kg,
    const float* __restrict__ Vg,
    float* __restrict__ O,
    unsigned* QsPs, unsigned* Ks, unsigned* Vs) {

    const int qbase = qt * 128;
    const int tid = threadIdx.x;
    const int lane = tid & 31;
    const int warp = tid >> 5;
    const int m0 = warp * 32;
    const int qr = lane >> 2;
    const int qc = lane & 3;
    const int f4 = tid & 15;
    const int row0 = tid >> 4;

    __syncthreads();   // prior tile's P/K/V reads complete before Q reload

    // ---- load Q tile (128 x 64) ----
#pragma unroll
    for (int i = 0; i < 16; ++i) {
        int r = row0 + i * 8;
        float4 v = *(const float4*)&Q[(size_t)(qbase + r) * QSTRIDE + h * D + f4 * 4];
        uint4 u = make_uint4(f2t(v.x), f2t(v.y), f2t(v.z), f2t(v.w));
        *(uint4*)&QsPs[r * FPQ + f4 * 4] = u;
    }
    __syncthreads();

    // ---- hoist Q fragments (loop-invariant) into registers ----
    unsigned qa[8][2][4];
#pragma unroll
    for (int ks = 0; ks < 8; ++ks) {
        const int k0 = ks * 8;
#pragma unroll
        for (int mt = 0; mt < 2; ++mt) {
            int m = m0 + mt * 16;
            qa[ks][mt][0] = QsPs[(m + qr) * FPQ + k0 + qc];
            qa[ks][mt][1] = QsPs[(m + 8 + qr) * FPQ + k0 + qc];
            qa[ks][mt][2] = QsPs[(m + qr) * FPQ + k0 + 4 + qc];
            qa[ks][mt][3] = QsPs[(m + 8 + qr) * FPQ + k0 + 4 + qc];
        }
    }
    // From here on, QsPs serves as the P buffer (warp-private rows).

    float o[2][8][4];
#pragma unroll
    for (int mt = 0; mt < 2; ++mt)
#pragma unroll
        for (int nt = 0; nt < 8; ++nt)
#pragma unroll
            for (int j = 0; j < 4; ++j) o[mt][nt][j] = 0.f;
    float mr[2][2], lr[2][2];
#pragma unroll
    for (int mt = 0; mt < 2; ++mt) {
        mr[mt][0] = -1e30f; mr[mt][1] = -1e30f;
        lr[mt][0] = 0.f;    lr[mt][1] = 0.f;
    }

    const int kt_max = 2 * qt + 1;
    for (int kt = 0; kt <= kt_max; ++kt) {
        __syncthreads();
        const int kbase = kt * 64;

        // load K tile (64 x 64)
#pragma unroll
        for (int i = 0; i < 8; ++i) {
            int r = row0 + i * 8;
            float4 v = *(const float4*)&Kg[(size_t)(kbase + r) * KSTRIDE + kh * D + f4 * 4];
            uint4 u = make_uint4(f2t(v.x), f2t(v.y), f2t(v.z), f2t(v.w));
            *(uint4*)&Ks[r * FPQ + f4 * 4] = u;
        }
        // load V tile (64 x 64) row-major [k][d]
#pragma unroll
        for (int i = 0; i < 8; ++i) {
            int r = row0 + i * 8;
            float4 v = *(const float4*)&Vg[(size_t)(kbase + r) * KSTRIDE + kh * D + f4 * 4];
            uint4 u = make_uint4(f2t(v.x), f2t(v.y), f2t(v.z), f2t(v.w));
            *(uint4*)&Vs[r * FPV + f4 * 4] = u;
        }
        __syncthreads();

        if (kbase > qbase + m0 + 31) continue;

        // ---- S = Q K^T (Q fragments from registers) ----
        float s[2][8][4];
#pragma unroll
        for (int mt = 0; mt < 2; ++mt)
#pragma unroll
            for (int nt = 0; nt < 8; ++nt)
#pragma unroll
                for (int j = 0; j < 4; ++j) s[mt][nt][j] = 0.f;

#pragma unroll
        for (int ks = 0; ks < 8; ++ks) {
            const int k0 = ks * 8;
#pragma unroll
            for (int nt = 0; nt < 8; ++nt) {
                unsigned b0 = Ks[(nt * 8 + qr) * FPQ + k0 + qc];
                unsigned b1 = Ks[(nt * 8 + qr) * FPQ + k0 + 4 + qc];
#pragma unroll
                for (int mt = 0; mt < 2; ++mt)
                    mma_tf32(s[mt][nt], qa[ks][mt][0], qa[ks][mt][1],
                             qa[ks][mt][2], qa[ks][mt][3], b0, b1);
            }
        }

        // ---- scale + causal mask + online softmax (per mt) ----
#pragma unroll
        for (int mt = 0; mt < 2; ++mt) {
            const int q_lo = qbase + m0 + mt * 16 + qr;
            const int q_hi = q_lo + 8;
            const bool need_mask = (kbase + 63 > q_lo);
#pragma unroll
            for (int nt = 0; nt < 8; ++nt) {
#pragma unroll
                for (int j = 0; j < 2; ++j) {
                    int kcol = kbase + nt * 8 + 2 * qc + j;
                    float v0 = s[mt][nt][j] * 0.125f;
                    float v1 = s[mt][nt][2 + j] * 0.125f;
                    if (need_mask && kcol > q_lo) v0 = -1e30f;
                    if (need_mask && kcol > q_hi) v1 = -1e30f;
                    s[mt][nt][j] = v0;
                    s[mt][nt][2 + j] = v1;
                }
            }

            float tm_lo = -1e30f, tm_hi = -1e30f;
#pragma unroll
            for (int nt = 0; nt < 8; ++nt) {
                tm_lo = fmaxf(tm_lo, fmaxf(s[mt][nt][0], s[mt][nt][1]));
                tm_hi = fmaxf(tm_hi, fmaxf(s[mt][nt][2], s[mt][nt][3]));
            }
#pragma unroll
            for (int off = 1; off <= 2; off <<= 1) {
                tm_lo = fmaxf(tm_lo, __shfl_xor_sync(0xffffffffu, tm_lo, off));
                tm_hi = fmaxf(tm_hi, __shfl_xor_sync(0xffffffffu, tm_hi, off));
            }
            float mn_lo = fmaxf(mr[mt][0], tm_lo);
            float mn_hi = fmaxf(mr[mt][1], tm_hi);
            float fac_lo = __expf(mr[mt][0] - mn_lo);
            float fac_hi = __expf(mr[mt][1] - mn_hi);

            float sum_lo = 0.f, sum_hi = 0.f;
#pragma unroll
            for (int nt = 0; nt < 8; ++nt) {
                float p0 = __expf(s[mt][nt][0] - mn_lo);
                float p1 = __expf(s[mt][nt][1] - mn_lo);
                float p2 = __expf(s[mt][nt][2] - mn_hi);
                float p3 = __expf(s[mt][nt][3] - mn_hi);
                s[mt][nt][0] = p0; s[mt][nt][1] = p1;
                s[mt][nt][2] = p2; s[mt][nt][3] = p3;
                sum_lo += p0 + p1;
                sum_hi += p2 + p3;
            }
#pragma unroll
            for (int off = 1; off <= 2; off <<= 1) {
                sum_lo += __shfl_xor_sync(0xffffffffu, sum_lo, off);
                sum_hi += __shfl_xor_sync(0xffffffffu, sum_hi, off);
            }
            lr[mt][0] = lr[mt][0] * fac_lo + sum_lo;
            lr[mt][1] = lr[mt][1] * fac_hi + sum_hi;
            mr[mt][0] = mn_lo;
            mr[mt][1] = mn_hi;

#pragma unroll
            for (int nt = 0; nt < 8; ++nt) {
                o[mt][nt][0] *= fac_lo; o[mt][nt][1] *= fac_lo;
                o[mt][nt][2] *= fac_hi; o[mt][nt][3] *= fac_hi;
            }

            // write P fragments to smem (warp-private rows, overlaid on Qs)
#pragma unroll
            for (int nt = 0; nt < 8; ++nt) {
                int r = m0 + mt * 16 + qr;
                int c = nt * 8 + 2 * qc;
                QsPs[r * FPQ + c]           = f2t(s[mt][nt][0]);
                QsPs[r * FPQ + c + 1]       = f2t(s[mt][nt][1]);
                QsPs[(r + 8) * FPQ + c]     = f2t(s[mt][nt][2]);
                QsPs[(r + 8) * FPQ + c + 1] = f2t(s[mt][nt][3]);
            }
        }
        __syncwarp();

        // ---- O += P V ----
#pragma unroll
        for (int ks = 0; ks < 8; ++ks) {
            const int k0 = ks * 8;
            unsigned a[2][4];
#pragma unroll
            for (int mt = 0; mt < 2; ++mt) {
                int m = m0 + mt * 16;
                a[mt][0] = QsPs[(m + qr) * FPQ + k0 + qc];
                a[mt][1] = QsPs[(m + 8 + qr) * FPQ + k0 + qc];
                a[mt][2] = QsPs[(m + qr) * FPQ + k0 + 4 + qc];
                a[mt][3] = QsPs[(m + 8 + qr) * FPQ + k0 + 4 + qc];
            }
#pragma unroll
            for (int nt = 0; nt < 8; ++nt) {
                unsigned b0 = Vs[(k0 + qc) * FPV + nt * 8 + qr];
                unsigned b1 = Vs[(k0 + 4 + qc) * FPV + nt * 8 + qr];
#pragma unroll
                for (int mt = 0; mt < 2; ++mt)
                    mma_tf32(o[mt][nt], a[mt][0], a[mt][1], a[mt][2], a[mt][3], b0, b1);
            }
        }
    }

    // ---- normalize + write out ----
#pragma unroll
    for (int mt = 0; mt < 2; ++mt) {
        float inv_lo = 1.f / lr[mt][0];
        float inv_hi = 1.f / lr[mt][1];
#pragma unroll
        for (int nt = 0; nt < 8; ++nt) {
            int row = qbase + m0 + mt * 16 + qr;
            int col = h * D + nt * 8 + 2 * qc;
            *(float2*)&O[(size_t)row * QSTRIDE + col] =
                make_float2(o[mt][nt][0] * inv_lo, o[mt][nt][1] * inv_lo);
            *(float2*)&O[(size_t)(row + 8) * QSTRIDE + col] =
                make_float2(o[mt][nt][2] * inv_hi, o[mt][nt][3] * inv_hi);
        }
    }
}

__global__ __launch_bounds__(128, 2)
void flash_tc_kernel(const float* __restrict__ Q,
                     const float* __restrict__ Kg,
                     const float* __restrict__ Vg,
                     float* __restrict__ O) {
    const int h = blockIdx.y;
    const int kh = h >> 2;
    const int NT = gridDim.x * 2;                // 16 q-tiles
    const int qt_heavy = NT - 1 - blockIdx.x;    // 15..8
    const int qt_light = blockIdx.x;             // 0..7

    extern __shared__ unsigned smu[];
    unsigned* QsPs = smu;
    unsigned* Ks   = QsPs + 128 * FPQ;
    unsigned* Vs   = Ks + 64 * FPQ;

    flash_one_tile(qt_heavy, h, kh, Q, Kg, Vg, O, QsPs, Ks, Vs);
    flash_one_tile(qt_light, h, kh, Q, Kg, Vg, O, QsPs, Ks, Vs);
}

// ---------------- launch ---------------------------------------------------
extern "C" void kernel_launch(void* const* d_in, const int* in_sizes, int n_in,
                              void* d_out, int out_size) {
    const float* x  = (const float*)d_in[0];
    const float* fc = (const float*)d_in[1];
    const float* Wq = (const float*)d_in[3];
    const float* Wk = (const float*)d_in[4];
    const float* Wv = (const float*)d_in[5];
    const float* Wo = (const float*)d_in[6];
    float* out = (float*)d_out;

    float *Q, *K, *V, *A;
    cudaGetSymbolAddress((void**)&Q, g_Q);
    cudaGetSymbolAddress((void**)&K, g_K);
    cudaGetSymbolAddress((void**)&V, g_V);
    cudaGetSymbolAddress((void**)&A, g_A);

    cudaFuncSetAttribute(qkv_gemm_kernel,
                         cudaFuncAttributeMaxDynamicSharedMemorySize, GEMM_SMEM_BYTES);
    cudaFuncSetAttribute(tgemm_kernel,
                         cudaFuncAttributeMaxDynamicSharedMemorySize, GEMM_SMEM_BYTES);
    cudaFuncSetAttribute(flash_tc_kernel,
                         cudaFuncAttributeMaxDynamicSharedMemorySize, FA_SMEM_BYTES);

    // fused QKV projection + RoPE (Q,K only)
    qkv_gemm_kernel<<<dim3(NTOT / 128, S / 128), 128, GEMM_SMEM_BYTES>>>(
        x, Wq, Wk, Wv, fc, Q, K, V);

    // causal GQA flash attention, paired q-tiles (balanced single wave)
    flash_tc_kernel<<<dim3(S / 256, HQ), 128, FA_SMEM_BYTES>>>(Q, K, V, A);

    // output projection
    tgemm_kernel<<<dim3(E / 128, S / 128), 128, GEMM_SMEM_BYTES>>>(A, Wo, out, S, E, E);
}